// round 16
// baseline (speedup 1.0000x reference)
#include <cuda_runtime.h>
#include <cuda_bf16.h>
#include <math.h>
#include <float.h>
#include <stdint.h>
#include <string.h>

#define KCOMP 64
#define DDIM  8
#define NC    36
#define TPB   128       // 4 warps
#define SPB   64        // samples per tile; warp owns 16 rows (1 m-tile)
#define NT    8         // 64 comps / n8
#define KT    3         // 48 feats / k16
#define WF_CNT (NT * KT * 32)   // 768 uint4
#define NBLK  740       // 148 SMs x 5 resident blocks: exactly one wave

__device__ __forceinline__ constexpr int TIX(int i, int j) { return i * (i + 1) / 2 + j; }

// scratch (no allocations allowed)
__device__ double   g_bsum[1024];
__device__ unsigned g_done = 0;

// feature index maps: f[j] = t[FA[j]] * t[FB[j]] for j<36
static __device__ constexpr int c_FA[36] =
    {0,0,0,0,0,0,0,0, 1,1,1,1,1,1,1, 2,2,2,2,2,2, 3,3,3,3,3, 4,4,4,4, 5,5,5, 6,6, 7};
static __device__ constexpr int c_FB[36] =
    {0,1,2,3,4,5,6,7, 1,2,3,4,5,6,7, 2,3,4,5,6,7, 3,4,5,6,7, 4,5,6,7, 5,6,7, 6,7, 7};

__device__ __forceinline__ float fval(const float* t, int j) {
    if (j < 36) return t[c_FA[j]] * t[c_FB[j]];
    if (j < 44) return t[j - 36];
    return (j == 44) ? 1.0f : 0.0f;
}

// XOR-swizzled feature-row index (uint4 units, row stride 16).
__device__ __forceinline__ int fs_idx(int row, int slot) {
    return row * 16 + (slot ^ ((row & 1) << 2) ^ ((row >> 1) & 3));
}

// ---------------------------------------------------------------------------
// helpers
// ---------------------------------------------------------------------------
__device__ __forceinline__ uint32_t pack_bf16x2(float a, float b) {
    __nv_bfloat162 h = __floats2bfloat162_rn(a, b);
    uint32_t u; memcpy(&u, &h, 4);
    return u;
}

__device__ __forceinline__ uint32_t prmt_hi(uint32_t a, uint32_t b) {
    uint32_t r;
    asm("prmt.b32 %0, %1, %2, 0x7632;" : "=r"(r) : "r"(a), "r"(b));
    return r;
}

__device__ __forceinline__ float trunc_bf(uint32_t u) {
    return __uint_as_float(u & 0xFFFF0000u);
}

__device__ __forceinline__ float bf_hi_rn(float x) {
    return __bfloat162float(__float2bfloat16_rn(x));
}

__device__ __forceinline__ void mma_bf16(float* c, uint32_t a0, uint32_t a1,
                                         uint32_t a2, uint32_t a3,
                                         uint32_t b0, uint32_t b1) {
    asm volatile(
        "mma.sync.aligned.m16n8k16.row.col.f32.bf16.bf16.f32 "
        "{%0,%1,%2,%3}, {%4,%5,%6,%7}, {%8,%9}, {%0,%1,%2,%3};"
        : "+f"(c[0]), "+f"(c[1]), "+f"(c[2]), "+f"(c[3])
        : "r"(a0), "r"(a1), "r"(a2), "r"(a3), "r"(b0), "r"(b1));
}

// ---------------------------------------------------------------------------
// Per-component weight build -> B-fragments straight into smem sWf.
// ---------------------------------------------------------------------------
__device__ void prep_component(int k, const float* __restrict__ mu,
                               const float* __restrict__ Lc, uint4* sWf) {
    float L[NC];
    #pragma unroll
    for (int i = 0; i < NC; ++i) L[i] = Lc[k * NC + i];

    float logdet = 0.f;
    #pragma unroll
    for (int i = 0; i < DDIM; ++i) logdet += logf(L[TIX(i, i)]);

    float dinv[DDIM];
    #pragma unroll
    for (int i = 0; i < DDIM; ++i) dinv[i] = 1.f / L[TIX(i, i)];

    float A[NC];
    #pragma unroll
    for (int j = 0; j < DDIM; ++j) {
        A[TIX(j, j)] = dinv[j];
        #pragma unroll
        for (int i = j + 1; i < DDIM; ++i) {
            float s = 0.f;
            #pragma unroll
            for (int mm = j; mm < i; ++mm) s += L[TIX(i, mm)] * A[TIX(mm, j)];
            A[TIX(i, j)] = -s * dinv[i];
        }
    }

    float mv[DDIM];
    #pragma unroll
    for (int j = 0; j < DDIM; ++j) mv[j] = mu[k * DDIM + j];

    float v[DDIM];
    #pragma unroll
    for (int i = 0; i < DDIM; ++i) {
        float s = 0.f;
        #pragma unroll
        for (int j = 0; j <= i; ++j) s += A[TIX(i, j)] * mv[j];
        v[i] = s;
    }
    float q[DDIM];
    #pragma unroll
    for (int a = 0; a < DDIM; ++a) {
        float s = 0.f;
        #pragma unroll
        for (int i = a; i < DDIM; ++i) s += A[TIX(i, a)] * v[i];
        q[a] = s;
    }
    float cc = 0.f;
    #pragma unroll
    for (int i = 0; i < DDIM; ++i) cc += v[i] * v[i];

    float w[48];
    {
        int p = 0;
        #pragma unroll
        for (int a = 0; a < DDIM; ++a) {
            #pragma unroll
            for (int b = a; b < DDIM; ++b) {
                float P = 0.f;
                #pragma unroll
                for (int i = b; i < DDIM; ++i) P += A[TIX(i, a)] * A[TIX(i, b)];
                w[p++] = (a == b) ? -0.5f * P : -P;   // folds 2x of off-diag
            }
        }
        #pragma unroll
        for (int a = 0; a < DDIM; ++a) w[NC + a] = q[a];
        const float NORM_CONST = -0.5f * (float)DDIM * 1.8378770664093453f;
        w[44] = NORM_CONST - logdet - 0.5f * cc;
        w[45] = 0.f; w[46] = 0.f; w[47] = 0.f;
    }

    // scatter with fused hi/lo split: col n = k; lane = (k&7)*4+tg; tile (k>>3,kt)
    const int nt = k >> 3;
    const int lb = (k & 7) * 4;
    #pragma unroll
    for (int kt = 0; kt < KT; ++kt) {
        #pragma unroll
        for (int tg = 0; tg < 4; ++tg) {
            int kb = 16 * kt + 2 * tg;
            float h0 = bf_hi_rn(w[kb]),     h1 = bf_hi_rn(w[kb + 1]);
            float h2 = bf_hi_rn(w[kb + 8]), h3 = bf_hi_rn(w[kb + 9]);
            uint4 bw;
            bw.x = pack_bf16x2(h0, h1);                          // b0 hi
            bw.y = pack_bf16x2(h2, h3);                          // b1 hi
            bw.z = pack_bf16x2(w[kb]     - h0, w[kb + 1] - h1);  // b0 lo
            bw.w = pack_bf16x2(w[kb + 8] - h2, w[kb + 9] - h3);  // b1 lo
            sWf[(nt * KT + kt) * 32 + lb + tg] = bw;
        }
    }
}

// ---------------------------------------------------------------------------
// Feature emit: slots [BASE, BASE+CNT), compile-time indices.
// ---------------------------------------------------------------------------
template <int BASE, int CNT>
__device__ __forceinline__ void emit_feats(uint4* FsU4, const float* t, int row) {
    #pragma unroll
    for (int si = 0; si < CNT; ++si) {
        const int slot = BASE + si;
        const int kt = slot >> 2, tg = slot & 3;
        const int p0 = 8 * kt + tg;
        float f0 = fval(t, 2 * p0),     f1 = fval(t, 2 * p0 + 1);
        float f2 = fval(t, 2 * p0 + 8), f3 = fval(t, 2 * p0 + 9);
        uint32_t u0 = __float_as_uint(f0), u1 = __float_as_uint(f1);
        uint32_t u2 = __float_as_uint(f2), u3 = __float_as_uint(f3);
        uint4 vv;
        vv.x = prmt_hi(u0, u1);
        vv.y = pack_bf16x2(f0 - trunc_bf(u0), f1 - trunc_bf(u1));
        vv.z = prmt_hi(u2, u3);
        vv.w = pack_bf16x2(f2 - trunc_bf(u2), f3 - trunc_bf(u3));
        FsU4[fs_idx(row, slot)] = vv;
    }
}

__device__ __forceinline__ void load_t(const float* __restrict__ target,
                                       int s, int B, float* t) {
    if (s < B) {
        float4 t0 = reinterpret_cast<const float4*>(target)[s * 2 + 0];
        float4 t1 = reinterpret_cast<const float4*>(target)[s * 2 + 1];
        t[0]=t0.x; t[1]=t0.y; t[2]=t0.z; t[3]=t0.w;
        t[4]=t1.x; t[5]=t1.y; t[6]=t1.z; t[7]=t1.w;
    } else {
        #pragma unroll
        for (int i = 0; i < DDIM; ++i) t[i] = 0.f;
    }
}

// ---------------------------------------------------------------------------
// Persistent single-wave kernel (740 = 148x5), R14 body + software pipeline:
// double-buffered feature tiles; per tile: MMA -> pi prefetch -> emit(next)
// -> epilogue -> one barrier.
// ---------------------------------------------------------------------------
__global__ void __launch_bounds__(TPB, 5) mdn_kernel(
    const float* __restrict__ pi,
    const float* __restrict__ mu,
    const float* __restrict__ Lc,
    const float* __restrict__ target,
    float* __restrict__ out,
    int B, int ntiles) {

    __shared__ uint4  FsU4[2][SPB * 16];  // 2 x 16 KB, swizzled feature rows
    __shared__ uint4  sWf[WF_CNT];        // 12 KB, B fragments
    __shared__ double red[TPB];           // 1 KB

    const int tid  = threadIdx.x;
    const int wid  = tid >> 5;
    const int lane = tid & 31;
    const int gid  = lane >> 2;   // 0..7
    const int tig  = lane & 3;    // 0..3
    const int rA   = wid * 16 + gid;

    const float2* pi2 = reinterpret_cast<const float2*>(pi);
    double contrib = 0.0;

    // ---- prologue: prep (warps 0-1) || emit tile #blockIdx.x into buf 0 ----
    {
        const int sbase = blockIdx.x * SPB;
        if (tid < KCOMP) {
            prep_component(tid, mu, Lc, sWf);
        } else {
            const int row = tid - 64;
            float t[DDIM];
            load_t(target, sbase + row, B, t);
            emit_feats<0, 12>(FsU4[0], t, row);
        }
    }
    __syncthreads();

    int it = 0;
    #pragma unroll 1
    for (int tile = blockIdx.x; tile < ntiles; tile += NBLK, ++it) {
        const int cur = it & 1;
        const int sbase = tile * SPB;
        const uint4* Fb = FsU4[cur];

        // ---- MMA: m16n64k48, 3 passes (hi*hi, lo*hi, hi*lo) ----
        float c[NT][4];
        #pragma unroll
        for (int nt = 0; nt < NT; ++nt)
            #pragma unroll
            for (int i = 0; i < 4; ++i) c[nt][i] = 0.f;

        #pragma unroll
        for (int kt = 0; kt < KT; ++kt) {
            uint4 A0 = Fb[fs_idx(rA,     kt * 4 + tig)];  // a0h,a0l,a2h,a2l
            uint4 A1 = Fb[fs_idx(rA + 8, kt * 4 + tig)];  // a1h,a1l,a3h,a3l
            #pragma unroll
            for (int nt = 0; nt < NT; ++nt) {
                uint4 bw = sWf[(nt * KT + kt) * 32 + lane];
                mma_bf16(c[nt], A0.x, A1.x, A0.z, A1.z, bw.x, bw.y); // hi*hi
                mma_bf16(c[nt], A0.y, A1.y, A0.w, A1.w, bw.x, bw.y); // lo*hi
                mma_bf16(c[nt], A0.x, A1.x, A0.z, A1.z, bw.z, bw.w); // hi*lo
            }
        }

        const int r0 = sbase + rA;        // c0/c1 row
        const int r1 = r0 + 8;            // c2/c3 row
        const int rr0 = (r0 < B) ? r0 : 0;
        const int rr1 = (r1 < B) ? r1 : 0;

        // ---- pi L2 prefetch (tig selects one of 4 half-lines of r0/r1) ----
        {
            int pr = (tig & 2) ? rr1 : rr0;
            const char* p = (const char*)(pi + (size_t)pr * 64) + (tig & 1) * 128;
            asm volatile("prefetch.global.L2 [%0];" :: "l"(p));
        }

        // ---- emit NEXT tile's features into the other buffer ----
        {
            const int ntile = tile + NBLK;
            if (ntile < ntiles) {
                const int row = tid & 63;
                float t[DDIM];
                load_t(target, ntile * SPB + row, B, t);
                if (tid < 64) emit_feats<0, 6>(FsU4[cur ^ 1], t, row);
                else          emit_feats<6, 6>(FsU4[cur ^ 1], t, row);
            }
        }

        // ---- per-row logsumexp with pi (lines now in L2) ----
        float mx0 = -FLT_MAX, mx1 = -FLT_MAX;
        #pragma unroll
        for (int nt = 0; nt < NT; ++nt) {
            mx0 = fmaxf(mx0, fmaxf(c[nt][0], c[nt][1]));
            mx1 = fmaxf(mx1, fmaxf(c[nt][2], c[nt][3]));
        }
        mx0 = fmaxf(mx0, __shfl_xor_sync(0xffffffff, mx0, 1));
        mx0 = fmaxf(mx0, __shfl_xor_sync(0xffffffff, mx0, 2));
        mx1 = fmaxf(mx1, __shfl_xor_sync(0xffffffff, mx1, 1));
        mx1 = fmaxf(mx1, __shfl_xor_sync(0xffffffff, mx1, 2));

        float S0 = 0.f, S1 = 0.f;
        #pragma unroll
        for (int nt = 0; nt < NT; ++nt) {
            float2 p0 = pi2[rr0 * 32 + nt * 4 + tig];
            float2 p1 = pi2[rr1 * 32 + nt * 4 + tig];
            S0 = fmaf(p0.x + 1e-10f, __expf(c[nt][0] - mx0), S0);
            S0 = fmaf(p0.y + 1e-10f, __expf(c[nt][1] - mx0), S0);
            S1 = fmaf(p1.x + 1e-10f, __expf(c[nt][2] - mx1), S1);
            S1 = fmaf(p1.y + 1e-10f, __expf(c[nt][3] - mx1), S1);
        }
        S0 += __shfl_xor_sync(0xffffffff, S0, 1);
        S0 += __shfl_xor_sync(0xffffffff, S0, 2);
        S1 += __shfl_xor_sync(0xffffffff, S1, 1);
        S1 += __shfl_xor_sync(0xffffffff, S1, 2);

        if (tig == 0) {
            if (r0 < B) contrib += (double)(mx0 + __logf(S0));
            if (r1 < B) contrib += (double)(mx1 + __logf(S1));
        }

        __syncthreads();   // all MMA reads of cur buf + emits of next buf done
    }

    // ---- reduce: warp shuffle, cross-warp, last-block finish ----
    #pragma unroll
    for (int off = 16; off > 0; off >>= 1)
        contrib += __shfl_xor_sync(0xffffffff, contrib, off);
    if (lane == 0) red[wid] = contrib;
    __syncthreads();

    __shared__ int sLast;
    if (tid == 0) {
        g_bsum[blockIdx.x] = red[0] + red[1] + red[2] + red[3];
        __threadfence();
        unsigned tkt = atomicAdd(&g_done, 1u);
        sLast = (tkt == gridDim.x - 1);
    }
    __syncthreads();

    if (sLast) {
        double s = 0.0;
        for (int i = tid; i < (int)gridDim.x; i += TPB) s += g_bsum[i];
        red[tid] = s;
        __syncthreads();
        #pragma unroll
        for (int st = TPB / 2; st > 0; st >>= 1) {
            if (tid < st) red[tid] += red[tid + st];
            __syncthreads();
        }
        if (tid == 0) {
            out[0] = (float)(-red[0] / (double)B);
            g_done = 0;            // reset for next graph replay
        }
    }
}

extern "C" void kernel_launch(void* const* d_in, const int* in_sizes, int n_in,
                              void* d_out, int out_size) {
    const float* pi     = (const float*)d_in[0];   // (B, 64)
    const float* mu     = (const float*)d_in[1];   // (64, 8)
    const float* Lc     = (const float*)d_in[2];   // (64, 36)
    const float* target = (const float*)d_in[3];   // (B, 8)

    int B = in_sizes[0] / KCOMP;

    int ntiles = (B + SPB - 1) / SPB;     // B=131072 -> 2048 tiles
    int grid = (ntiles < NBLK) ? ntiles : NBLK;

    mdn_kernel<<<grid, TPB>>>(pi, mu, Lc, target, (float*)d_out, B, ntiles);
}

// round 17
// speedup vs baseline: 1.1598x; 1.1598x over previous
#include <cuda_runtime.h>
#include <cuda_bf16.h>
#include <math.h>
#include <float.h>
#include <stdint.h>
#include <string.h>

#define KCOMP 64
#define DDIM  8
#define NC    36
#define TPB   128       // 4 warps
#define SPB   64        // samples per tile; warp owns 16 rows (1 m-tile)
#define NT    8         // 64 comps / n8
#define KT    3         // 48 feats / k16
#define WF_CNT (NT * KT * 32)   // 768 uint4
#define NBLK  740       // 148 SMs x 5 resident blocks: exactly one wave

__device__ __forceinline__ constexpr int TIX(int i, int j) { return i * (i + 1) / 2 + j; }

// scratch (no allocations allowed)
__device__ double   g_bsum[1024];
__device__ unsigned g_done = 0;

// feature index maps: f[j] = t[FA[j]] * t[FB[j]] for j<36
static __device__ constexpr int c_FA[36] =
    {0,0,0,0,0,0,0,0, 1,1,1,1,1,1,1, 2,2,2,2,2,2, 3,3,3,3,3, 4,4,4,4, 5,5,5, 6,6, 7};
static __device__ constexpr int c_FB[36] =
    {0,1,2,3,4,5,6,7, 1,2,3,4,5,6,7, 2,3,4,5,6,7, 3,4,5,6,7, 4,5,6,7, 5,6,7, 6,7, 7};

__device__ __forceinline__ float fval(const float* t, int j) {
    if (j < 36) return t[c_FA[j]] * t[c_FB[j]];
    if (j < 44) return t[j - 36];
    return (j == 44) ? 1.0f : 0.0f;
}

// XOR-swizzled feature-row index (uint4 units, row stride 16).
__device__ __forceinline__ int fs_idx(int row, int slot) {
    return row * 16 + (slot ^ ((row & 1) << 2) ^ ((row >> 1) & 3));
}

// ---------------------------------------------------------------------------
// helpers
// ---------------------------------------------------------------------------
__device__ __forceinline__ uint32_t pack_bf16x2(float a, float b) {
    __nv_bfloat162 h = __floats2bfloat162_rn(a, b);
    uint32_t u; memcpy(&u, &h, 4);
    return u;
}

__device__ __forceinline__ uint32_t prmt_hi(uint32_t a, uint32_t b) {
    uint32_t r;
    asm("prmt.b32 %0, %1, %2, 0x7632;" : "=r"(r) : "r"(a), "r"(b));
    return r;
}

__device__ __forceinline__ float trunc_bf(uint32_t u) {
    return __uint_as_float(u & 0xFFFF0000u);
}

__device__ __forceinline__ float bf_hi_rn(float x) {
    return __bfloat162float(__float2bfloat16_rn(x));
}

__device__ __forceinline__ void mma_bf16(float* c, uint32_t a0, uint32_t a1,
                                         uint32_t a2, uint32_t a3,
                                         uint32_t b0, uint32_t b1) {
    asm volatile(
        "mma.sync.aligned.m16n8k16.row.col.f32.bf16.bf16.f32 "
        "{%0,%1,%2,%3}, {%4,%5,%6,%7}, {%8,%9}, {%0,%1,%2,%3};"
        : "+f"(c[0]), "+f"(c[1]), "+f"(c[2]), "+f"(c[3])
        : "r"(a0), "r"(a1), "r"(a2), "r"(a3), "r"(b0), "r"(b1));
}

// ---------------------------------------------------------------------------
// Per-component weight build -> B-fragments straight into smem sWf.
// ---------------------------------------------------------------------------
__device__ void prep_component(int k, const float* __restrict__ mu,
                               const float* __restrict__ Lc, uint4* sWf) {
    float L[NC];
    #pragma unroll
    for (int i = 0; i < NC; ++i) L[i] = Lc[k * NC + i];

    float logdet = 0.f;
    #pragma unroll
    for (int i = 0; i < DDIM; ++i) logdet += logf(L[TIX(i, i)]);

    float dinv[DDIM];
    #pragma unroll
    for (int i = 0; i < DDIM; ++i) dinv[i] = 1.f / L[TIX(i, i)];

    float A[NC];
    #pragma unroll
    for (int j = 0; j < DDIM; ++j) {
        A[TIX(j, j)] = dinv[j];
        #pragma unroll
        for (int i = j + 1; i < DDIM; ++i) {
            float s = 0.f;
            #pragma unroll
            for (int mm = j; mm < i; ++mm) s += L[TIX(i, mm)] * A[TIX(mm, j)];
            A[TIX(i, j)] = -s * dinv[i];
        }
    }

    float mv[DDIM];
    #pragma unroll
    for (int j = 0; j < DDIM; ++j) mv[j] = mu[k * DDIM + j];

    float v[DDIM];
    #pragma unroll
    for (int i = 0; i < DDIM; ++i) {
        float s = 0.f;
        #pragma unroll
        for (int j = 0; j <= i; ++j) s += A[TIX(i, j)] * mv[j];
        v[i] = s;
    }
    float q[DDIM];
    #pragma unroll
    for (int a = 0; a < DDIM; ++a) {
        float s = 0.f;
        #pragma unroll
        for (int i = a; i < DDIM; ++i) s += A[TIX(i, a)] * v[i];
        q[a] = s;
    }
    float cc = 0.f;
    #pragma unroll
    for (int i = 0; i < DDIM; ++i) cc += v[i] * v[i];

    float w[48];
    {
        int p = 0;
        #pragma unroll
        for (int a = 0; a < DDIM; ++a) {
            #pragma unroll
            for (int b = a; b < DDIM; ++b) {
                float P = 0.f;
                #pragma unroll
                for (int i = b; i < DDIM; ++i) P += A[TIX(i, a)] * A[TIX(i, b)];
                w[p++] = (a == b) ? -0.5f * P : -P;   // folds 2x of off-diag
            }
        }
        #pragma unroll
        for (int a = 0; a < DDIM; ++a) w[NC + a] = q[a];
        const float NORM_CONST = -0.5f * (float)DDIM * 1.8378770664093453f;
        w[44] = NORM_CONST - logdet - 0.5f * cc;
        w[45] = 0.f; w[46] = 0.f; w[47] = 0.f;
    }

    // scatter with fused hi/lo split: col n = k; lane = (k&7)*4+tg; tile (k>>3,kt)
    const int nt = k >> 3;
    const int lb = (k & 7) * 4;
    #pragma unroll
    for (int kt = 0; kt < KT; ++kt) {
        #pragma unroll
        for (int tg = 0; tg < 4; ++tg) {
            int kb = 16 * kt + 2 * tg;
            float h0 = bf_hi_rn(w[kb]),     h1 = bf_hi_rn(w[kb + 1]);
            float h2 = bf_hi_rn(w[kb + 8]), h3 = bf_hi_rn(w[kb + 9]);
            uint4 bw;
            bw.x = pack_bf16x2(h0, h1);                          // b0 hi
            bw.y = pack_bf16x2(h2, h3);                          // b1 hi
            bw.z = pack_bf16x2(w[kb]     - h0, w[kb + 1] - h1);  // b0 lo
            bw.w = pack_bf16x2(w[kb + 8] - h2, w[kb + 9] - h3);  // b1 lo
            sWf[(nt * KT + kt) * 32 + lb + tg] = bw;
        }
    }
}

// ---------------------------------------------------------------------------
// Feature emit: slots [BASE, BASE+CNT), compile-time indices.
// ---------------------------------------------------------------------------
template <int BASE, int CNT>
__device__ __forceinline__ void emit_feats(uint4* FsU4, const float* t, int row) {
    #pragma unroll
    for (int si = 0; si < CNT; ++si) {
        const int slot = BASE + si;
        const int kt = slot >> 2, tg = slot & 3;
        const int p0 = 8 * kt + tg;
        float f0 = fval(t, 2 * p0),     f1 = fval(t, 2 * p0 + 1);
        float f2 = fval(t, 2 * p0 + 8), f3 = fval(t, 2 * p0 + 9);
        uint32_t u0 = __float_as_uint(f0), u1 = __float_as_uint(f1);
        uint32_t u2 = __float_as_uint(f2), u3 = __float_as_uint(f3);
        uint4 vv;
        vv.x = prmt_hi(u0, u1);
        vv.y = pack_bf16x2(f0 - trunc_bf(u0), f1 - trunc_bf(u1));
        vv.z = prmt_hi(u2, u3);
        vv.w = pack_bf16x2(f2 - trunc_bf(u2), f3 - trunc_bf(u3));
        FsU4[fs_idx(row, slot)] = vv;
    }
}

__device__ __forceinline__ void load_t(const float* __restrict__ target,
                                       int s, int B, float* t) {
    if (s < B) {
        float4 t0 = reinterpret_cast<const float4*>(target)[s * 2 + 0];
        float4 t1 = reinterpret_cast<const float4*>(target)[s * 2 + 1];
        t[0]=t0.x; t[1]=t0.y; t[2]=t0.z; t[3]=t0.w;
        t[4]=t1.x; t[5]=t1.y; t[6]=t1.z; t[7]=t1.w;
    } else {
        #pragma unroll
        for (int i = 0; i < DDIM; ++i) t[i] = 0.f;
    }
}

// ---------------------------------------------------------------------------
// Persistent single-wave kernel (740 blocks = 148x5), R14 body + pi prefetch
// before MMA + hoisted invariant smem addresses.
// ---------------------------------------------------------------------------
__global__ void __launch_bounds__(TPB, 5) mdn_kernel(
    const float* __restrict__ pi,
    const float* __restrict__ mu,
    const float* __restrict__ Lc,
    const float* __restrict__ target,
    float* __restrict__ out,
    int B, int ntiles) {

    __shared__ uint4  FsU4[SPB * 16];     // 16 KB, swizzled feature rows
    __shared__ uint4  sWf[WF_CNT];        // 12 KB, B fragments
    __shared__ double red[TPB];           // 1 KB

    const int tid  = threadIdx.x;
    const int wid  = tid >> 5;
    const int lane = tid & 31;
    const int gid  = lane >> 2;   // 0..7
    const int tig  = lane & 3;    // 0..3
    const int rA   = wid * 16 + gid;

    const float2* pi2 = reinterpret_cast<const float2*>(pi);
    double contrib = 0.0;

    // hoisted loop-invariant smem pointers (A fragments + B fragment bases)
    const uint4* A0p[KT];
    const uint4* A1p[KT];
    const uint4* Bp [KT];
    #pragma unroll
    for (int kt = 0; kt < KT; ++kt) {
        A0p[kt] = &FsU4[fs_idx(rA,     kt * 4 + tig)];
        A1p[kt] = &FsU4[fs_idx(rA + 8, kt * 4 + tig)];
        Bp [kt] = &sWf[kt * 32 + lane];
    }

    // ---- first tile: prep (warps 0-1) || feature emit (warps 2-3) ----
    {
        const int sbase = blockIdx.x * SPB;
        if (tid < KCOMP) {
            prep_component(tid, mu, Lc, sWf);
        } else {
            const int row = tid - 64;
            float t[DDIM];
            load_t(target, sbase + row, B, t);
            emit_feats<0, 12>(FsU4, t, row);
        }
    }
    __syncthreads();

    bool first = true;
    #pragma unroll 1
    for (int tile = blockIdx.x; tile < ntiles; tile += NBLK) {
        const int sbase = tile * SPB;

        if (!first) {
            __syncthreads();   // previous MMA reads done before overwrite
            const int row = tid & 63;
            float t[DDIM];
            load_t(target, sbase + row, B, t);
            if (tid < 64) emit_feats<0, 6>(FsU4, t, row);
            else          emit_feats<6, 6>(FsU4, t, row);
            __syncthreads();
        }
        first = false;

        const int r0 = sbase + rA;        // c0/c1 row
        const int r1 = r0 + 8;            // c2/c3 row
        const int rr0 = (r0 < B) ? r0 : 0;
        const int rr1 = (r1 < B) ? r1 : 0;

        // ---- pi L2 prefetch BEFORE MMA: warp's 4 quads cover both rows'
        //      two 128B half-lines; MMA (~1.5k cyc) hides DRAM->L2 ----
        {
            int pr = (tig & 2) ? rr1 : rr0;
            const char* p = (const char*)(pi + (size_t)pr * 64) + (tig & 1) * 128;
            asm volatile("prefetch.global.L2 [%0];" :: "l"(p));
        }

        // ---- MMA: m16n64k48, 3 passes (hi*hi, lo*hi, hi*lo) ----
        float c[NT][4];
        #pragma unroll
        for (int nt = 0; nt < NT; ++nt)
            #pragma unroll
            for (int i = 0; i < 4; ++i) c[nt][i] = 0.f;

        #pragma unroll
        for (int kt = 0; kt < KT; ++kt) {
            uint4 A0 = *A0p[kt];          // a0h,a0l,a2h,a2l
            uint4 A1 = *A1p[kt];          // a1h,a1l,a3h,a3l
            #pragma unroll
            for (int nt = 0; nt < NT; ++nt) {
                uint4 bw = Bp[kt][nt * (KT * 32)];
                mma_bf16(c[nt], A0.x, A1.x, A0.z, A1.z, bw.x, bw.y); // hi*hi
                mma_bf16(c[nt], A0.y, A1.y, A0.w, A1.w, bw.x, bw.y); // lo*hi
                mma_bf16(c[nt], A0.x, A1.x, A0.z, A1.z, bw.z, bw.w); // hi*lo
            }
        }

        // ---- per-row logsumexp with pi (lines now in L2) ----
        float mx0 = -FLT_MAX, mx1 = -FLT_MAX;
        #pragma unroll
        for (int nt = 0; nt < NT; ++nt) {
            mx0 = fmaxf(mx0, fmaxf(c[nt][0], c[nt][1]));
            mx1 = fmaxf(mx1, fmaxf(c[nt][2], c[nt][3]));
        }
        mx0 = fmaxf(mx0, __shfl_xor_sync(0xffffffff, mx0, 1));
        mx0 = fmaxf(mx0, __shfl_xor_sync(0xffffffff, mx0, 2));
        mx1 = fmaxf(mx1, __shfl_xor_sync(0xffffffff, mx1, 1));
        mx1 = fmaxf(mx1, __shfl_xor_sync(0xffffffff, mx1, 2));

        float S0 = 0.f, S1 = 0.f;
        #pragma unroll
        for (int nt = 0; nt < NT; ++nt) {
            float2 p0 = pi2[rr0 * 32 + nt * 4 + tig];
            float2 p1 = pi2[rr1 * 32 + nt * 4 + tig];
            S0 = fmaf(p0.x + 1e-10f, __expf(c[nt][0] - mx0), S0);
            S0 = fmaf(p0.y + 1e-10f, __expf(c[nt][1] - mx0), S0);
            S1 = fmaf(p1.x + 1e-10f, __expf(c[nt][2] - mx1), S1);
            S1 = fmaf(p1.y + 1e-10f, __expf(c[nt][3] - mx1), S1);
        }
        S0 += __shfl_xor_sync(0xffffffff, S0, 1);
        S0 += __shfl_xor_sync(0xffffffff, S0, 2);
        S1 += __shfl_xor_sync(0xffffffff, S1, 1);
        S1 += __shfl_xor_sync(0xffffffff, S1, 2);

        if (tig == 0) {
            if (r0 < B) contrib += (double)(mx0 + __logf(S0));
            if (r1 < B) contrib += (double)(mx1 + __logf(S1));
        }
    }

    // ---- reduce: warp shuffle, cross-warp, last-block finish ----
    #pragma unroll
    for (int off = 16; off > 0; off >>= 1)
        contrib += __shfl_xor_sync(0xffffffff, contrib, off);
    if (lane == 0) red[wid] = contrib;
    __syncthreads();

    __shared__ int sLast;
    if (tid == 0) {
        g_bsum[blockIdx.x] = red[0] + red[1] + red[2] + red[3];
        __threadfence();
        unsigned tkt = atomicAdd(&g_done, 1u);
        sLast = (tkt == gridDim.x - 1);
    }
    __syncthreads();

    if (sLast) {
        double s = 0.0;
        for (int i = tid; i < (int)gridDim.x; i += TPB) s += g_bsum[i];
        red[tid] = s;
        __syncthreads();
        #pragma unroll
        for (int st = TPB / 2; st > 0; st >>= 1) {
            if (tid < st) red[tid] += red[tid + st];
            __syncthreads();
        }
        if (tid == 0) {
            out[0] = (float)(-red[0] / (double)B);
            g_done = 0;            // reset for next graph replay
        }
    }
}

extern "C" void kernel_launch(void* const* d_in, const int* in_sizes, int n_in,
                              void* d_out, int out_size) {
    const float* pi     = (const float*)d_in[0];   // (B, 64)
    const float* mu     = (const float*)d_in[1];   // (64, 8)
    const float* Lc     = (const float*)d_in[2];   // (64, 36)
    const float* target = (const float*)d_in[3];   // (B, 8)

    int B = in_sizes[0] / KCOMP;

    int ntiles = (B + SPB - 1) / SPB;     // B=131072 -> 2048 tiles
    int grid = (ntiles < NBLK) ? ntiles : NBLK;

    mdn_kernel<<<grid, TPB>>>(pi, mu, Lc, target, (float*)d_out, B, ntiles);
}